// round 14
// baseline (speedup 1.0000x reference)
#include <cuda_runtime.h>

// ContConv1dDenseSim: out[b,l,o] = sum_{j in band, i} feat[b,j,i] * kv(dt_{l,j})[i,o]
// kv = MLP(relu) on scalar dt; banded causal mask (width 30); true_ids column mask;
// row-validity l <= 6*(len-1).
//
// Refactor (exact): FW2[j,h,o] = sum_i feat[j,i]*w2[h,i*16+o]; FB2[j,o] = sum_i feat[j,i]*b2[i*16+o]
// out[l,o] = sum_{j in band} ( FB2[j,o] + sum_h relu(dt*w1_h + b1_h) * FW2[j,h,o] )
//
// R14 == R13 resubmit (infra failure, no signal). Retile: block = 16 l-rows x
// 4 o-cols, grid (32, 2, 4) = 256 blocks x 512 thr -> 2 CTAs/SM (barrier-stall
// overlap) and phase-1 redundancy 4.6x -> 2.8x (total phase-1 dots -40%).
// FULL specialization for blockIdx.x >= 2.

namespace cc {
constexpr int LEN     = 512;
constexpr int BSZ     = 2;
constexpr int IN_CH   = 16;
constexpr int OUT_CH  = 16;
constexpr int HID     = 8;
constexpr int BAND    = 30;                 // j in [l-29, l]
constexpr int TILE_L  = 16;
constexpr int OBLK    = 4;                  // o-columns per block
constexpr int NJMAX   = BAND - 1 + TILE_L;  // 45
constexpr int OSTR    = 12;                 // 8 FW2 + FB2 + pad (16B aligned)
constexpr int JSTR    = OBLK * OSTR;        // 48 floats per jr row
constexpr int W2STR   = 260;                // 260 % 32 == 4 -> h*4 bank offsets, conflict-free
constexpr int NTHR    = 512;
constexpr int NGRP    = 8;
}

__global__ __launch_bounds__(512, 2)
void cc1d_fused_kernel(const float* __restrict__ times,
                       const float* __restrict__ features,
                       const int* __restrict__ lengths_i32,   // int32 or int64 layout
                       const void* __restrict__ true_ids_raw, // u8 or int32 layout
                       const float* __restrict__ w1,
                       const float* __restrict__ b1,
                       const float* __restrict__ w2,
                       const float* __restrict__ b2,
                       float* __restrict__ out)
{
    using namespace cc;
    __shared__ __align__(16) float feats[NJMAX * IN_CH];
    __shared__ __align__(16) float fw2s[NJMAX * JSTR];
    __shared__ __align__(16) float w2s[HID * W2STR];
    __shared__ __align__(16) float b2s[IN_CH * OUT_CH];      // [i*16+o]
    __shared__ float ts[NJMAX];
    __shared__ float w1s[HID], b1s[HID];
    __shared__ float partial[(NGRP - 1) * TILE_L * OBLK];

    const int b       = blockIdx.y;
    const int l_start = blockIdx.x * TILE_L;
    const int o_base  = blockIdx.z * OBLK;
    const bool FULL   = (blockIdx.x >= 2);    // l_start >= 32 > 29: band never clips
    const int t       = threadIdx.x;
    const int lane    = t & 31;

    // phase-1 mapping: warp == row-group rg (t>>5), lanes = 8h x 4ol
    const int rg  = t >> 5;                 // 0..15
    const int h1  = (t >> 2) & 7;           // hidden unit
    const int ol  = t & 3;                  // o within block
    // phase-2 mapping: g = band-chunk, ll = l_local, same ol
    const int g   = t >> 6;                 // 0..7
    const int ll  = (t >> 2) & 15;          // 0..15

    const int j0 = FULL ? (l_start - (BAND - 1)) : 0;
    const int nj = FULL ? NJMAX : (l_start + TILE_L);

    // ---- (1) barrier-critical first: feats float4 (nj*4 <= 180 threads, 1 iter) ----
    float4 fv = make_float4(0.f, 0.f, 0.f, 0.f);
    const int j_f  = j0 + (t >> 2);
    const bool do_feat = (t < nj * 4);
    if (do_feat)
        fv = ((const float4*)features)[(b * LEN + j_f) * 4 + (t & 3)];

    // ---- (2) layout detection: 1 LDG/thread over first 128B (L1/L2-shared).
    // int32-bool values are 0/1 => any nonzero byte above byte-0 => byte layout.
    const unsigned int v0 = ((const unsigned int*)true_ids_raw)[lane];

    // ---- (3) cooperative staging (contiguous, few wavefronts) ----
    {   // w2: 2048 floats as float4 into padded-stride shared (all 512 threads)
        const float4 wv = ((const float4*)w2)[t];
        const int hh = t >> 6, c4 = t & 63;
        *(float4*)&w2s[hh * W2STR + c4 * 4] = wv;
    }
    if (t < 64) {        // b2: 256 floats as float4
        ((float4*)b2s)[t] = ((const float4*)b2)[t];
    }
    else if (t < 64 + HID) { w1s[t - 64] = w1[t - 64]; b1s[t - 64] = b1[t - 64]; }
    else if (t >= 96 && t - 96 < nj) ts[t - 96] = times[b * LEN + j0 + (t - 96)];

    int len_pref = 0;    // only g==0 (t<64) stores output
    if (t < 64) {
        const int hw = __ldg(&lengths_i32[1]);   // hi word 0 <=> int64 (lengths >= 1)
        len_pref = (hw == 0) ? __ldg(&lengths_i32[2 * b]) : __ldg(&lengths_i32[b]);
    }

    // ---- resolve detection, fetch mask byte, select, store feats ----
    const bool byte_layout =
        __ballot_sync(0xFFFFFFFFu, (v0 & 0xFFFFFF00u) != 0u) != 0u;
    if (do_feat) {
        // LSB byte of an int32 bool equals its value (little-endian)
        const int bidx = (b * LEN + j_f) << (byte_layout ? 0 : 2);
        if (((const unsigned char*)true_ids_raw)[bidx] == 0)
            fv = make_float4(0.f, 0.f, 0.f, 0.f);
        ((float4*)feats)[t] = fv;
    }
    __syncthreads();   // feats, ts, w1s, b2s, w2s visible

    // per-thread w2 column from shared (stride 260 => h*4 bank offset + o: conflict-free)
    const int o = o_base + ol;
    float w2col[IN_CH];
    #pragma unroll
    for (int i = 0; i < IN_CH; i++)
        w2col[i] = w2s[h1 * W2STR + i * 16 + o];

    // ---- phase-1 row dot: FW2[jr][ol][h1] (+FB2 on h1==jr%8) ----
    auto p1row = [&](int jr) {
        const float4* fj4 = (const float4*)&feats[jr * IN_CH];   // warp-broadcast
        float4 fa = fj4[0], fb = fj4[1], fc = fj4[2], fd = fj4[3];
        float aA = 0.0f, aB = 0.0f;
        aA = fmaf(fa.x, w2col[0], aA); aB = fmaf(fb.x, w2col[4], aB);
        aA = fmaf(fa.y, w2col[1], aA); aB = fmaf(fb.y, w2col[5], aB);
        aA = fmaf(fa.z, w2col[2], aA); aB = fmaf(fb.z, w2col[6], aB);
        aA = fmaf(fa.w, w2col[3], aA); aB = fmaf(fb.w, w2col[7], aB);
        aA = fmaf(fc.x, w2col[8],  aA); aB = fmaf(fd.x, w2col[12], aB);
        aA = fmaf(fc.y, w2col[9],  aA); aB = fmaf(fd.y, w2col[13], aB);
        aA = fmaf(fc.z, w2col[10], aA); aB = fmaf(fd.z, w2col[14], aB);
        aA = fmaf(fc.w, w2col[11], aA); aB = fmaf(fd.w, w2col[15], aB);
        fw2s[jr * JSTR + ol * OSTR + h1] = aA + aB;
        if (h1 == (jr & 7)) {
            float bA = 0.0f, bB = 0.0f;
            bA = fmaf(fa.x, b2s[0 * 16 + o],  bA); bB = fmaf(fb.x, b2s[4 * 16 + o],  bB);
            bA = fmaf(fa.y, b2s[1 * 16 + o],  bA); bB = fmaf(fb.y, b2s[5 * 16 + o],  bB);
            bA = fmaf(fa.z, b2s[2 * 16 + o],  bA); bB = fmaf(fb.z, b2s[6 * 16 + o],  bB);
            bA = fmaf(fa.w, b2s[3 * 16 + o],  bA); bB = fmaf(fb.w, b2s[7 * 16 + o],  bB);
            bA = fmaf(fc.x, b2s[8 * 16 + o],  bA); bB = fmaf(fd.x, b2s[12 * 16 + o], bB);
            bA = fmaf(fc.y, b2s[9 * 16 + o],  bA); bB = fmaf(fd.y, b2s[13 * 16 + o], bB);
            bA = fmaf(fc.z, b2s[10 * 16 + o], bA); bB = fmaf(fd.z, b2s[14 * 16 + o], bB);
            bA = fmaf(fc.w, b2s[11 * 16 + o], bA); bB = fmaf(fd.w, b2s[15 * 16 + o], bB);
            fw2s[jr * JSTR + ol * OSTR + 8] = bA + bB;
        }
    };

    // ---- phase-2 band element accumulate ----
    float acc0 = 0.0f, acc1 = 0.0f;
    float w1r[HID], b1r[HID];
    #pragma unroll
    for (int k = 0; k < HID; k++) { w1r[k] = w1s[k]; b1r[k] = b1s[k]; }
    auto p2elem = [&](float tl, int jr) {
        const float dt = tl - ts[jr];
        const float* frp = &fw2s[jr * JSTR + ol * OSTR];
        const float4 fA = *(const float4*)frp;        // FW2 h=0..3
        const float4 fB = *(const float4*)(frp + 4);  // FW2 h=4..7
        float a0 = frp[8];                            // FB2 term
        float a1 = 0.0f;
        float hv;
        hv = fmaf(dt, w1r[0], b1r[0]); hv = hv > 0.f ? hv : 0.f; a0 = fmaf(hv, fA.x, a0);
        hv = fmaf(dt, w1r[1], b1r[1]); hv = hv > 0.f ? hv : 0.f; a1 = fmaf(hv, fA.y, a1);
        hv = fmaf(dt, w1r[2], b1r[2]); hv = hv > 0.f ? hv : 0.f; a0 = fmaf(hv, fA.z, a0);
        hv = fmaf(dt, w1r[3], b1r[3]); hv = hv > 0.f ? hv : 0.f; a1 = fmaf(hv, fA.w, a1);
        hv = fmaf(dt, w1r[4], b1r[4]); hv = hv > 0.f ? hv : 0.f; a0 = fmaf(hv, fB.x, a0);
        hv = fmaf(dt, w1r[5], b1r[5]); hv = hv > 0.f ? hv : 0.f; a1 = fmaf(hv, fB.y, a1);
        hv = fmaf(dt, w1r[6], b1r[6]); hv = hv > 0.f ? hv : 0.f; a0 = fmaf(hv, fB.z, a0);
        hv = fmaf(dt, w1r[7], b1r[7]); hv = hv > 0.f ? hv : 0.f; a1 = fmaf(hv, fB.w, a1);
        acc0 += a0; acc1 += a1;
    };

    if (FULL) {
        // phase 1: 45 rows over 16 row-groups x 3 (rg 0..14 full, rg 15 idle)
        {
            const int jr_base = rg * 3;
            if (rg < 15) { p1row(jr_base); p1row(jr_base + 1); p1row(jr_base + 2); }
        }
        __syncthreads();

        // phase 2: band exactly [ll, ll+29]; g<7 -> 4 elems, g==7 -> 2
        const float tl = ts[ll + (BAND - 1)];
        const int js = ll + g * 4;
        if (g < 7) {
            p2elem(tl, js);     p2elem(tl, js + 1);
            p2elem(tl, js + 2); p2elem(tl, js + 3);
        } else {
            p2elem(tl, js);     p2elem(tl, js + 1);
        }
    } else {
        // generic edge path (blockIdx.x < 2): j0 == 0, nj = l_start + 16
        {
            const int jr_base = rg * 3;
            #pragma unroll
            for (int u = 0; u < 3; u++) {
                const int jr = jr_base + u;
                if (jr < nj) p1row(jr);
            }
        }
        __syncthreads();

        const int lr = l_start + ll;          // j0 == 0
        const float tl = ts[lr];
        int jr_lo = lr - (BAND - 1); if (jr_lo < 0) jr_lo = 0;
        const int js = jr_lo + g * 4;
        #pragma unroll
        for (int u = 0; u < 4; u++) {
            const int jr = js + u;
            if (jr <= lr) p2elem(tl, jr);
        }
    }
    float acc = acc0 + acc1;

    const int m = ll * OBLK + ol;             // 0..63 output slot in block
    if (g > 0) partial[(g - 1) * 64 + m] = acc;
    __syncthreads();

    if (g == 0) {
        float p0 = partial[m]          + partial[64 + m];
        float p1 = partial[2 * 64 + m] + partial[3 * 64 + m];
        float p2 = partial[4 * 64 + m] + partial[5 * 64 + m];
        acc += (p0 + p1) + (p2 + partial[6 * 64 + m]);
        const int l = l_start + ll;
        const bool valid = l <= 6 * (len_pref - 1);
        out[(b * LEN + l) * OUT_CH + o] = valid ? acc : 0.0f;
    }
}

extern "C" void kernel_launch(void* const* d_in, const int* in_sizes, int n_in,
                              void* d_out, int out_size) {
    using namespace cc;
    // dict order: times, features, lengths, true_ids, [sim_size], w1, b1, w2, b2
    const float* times    = (const float*)d_in[0];
    const float* features = (const float*)d_in[1];
    const int*   lengths  = (const int*)d_in[2];
    const void*  tids     = d_in[3];

    int base = 4;
    if (n_in >= 9 && in_sizes[4] == 1) base = 5;  // sim_size scalar occupies slot 4

    const float* w1 = (const float*)d_in[base + 0];
    const float* b1 = (const float*)d_in[base + 1];
    const float* w2 = (const float*)d_in[base + 2];
    const float* b2 = (const float*)d_in[base + 3];
    float*       out = (float*)d_out;

    dim3 grid(LEN / TILE_L, BSZ, OUT_CH / OBLK);   // 32 x 2 x 4 = 256 blocks
    cc1d_fused_kernel<<<grid, NTHR>>>(times, features, lengths, tids,
                                      w1, b1, w2, b2, out);
}

// round 15
// speedup vs baseline: 1.0036x; 1.0036x over previous
#include <cuda_runtime.h>

// ContConv1dDenseSim: out[b,l,o] = sum_{j in band, i} feat[b,j,i] * kv(dt_{l,j})[i,o]
// kv = MLP(relu) on scalar dt; banded causal mask (width 30); true_ids column mask;
// row-validity l <= 6*(len-1).
//
// Refactor (exact): FW2[j,h,o] = sum_i feat[j,i]*w2[h,i*16+o]; FB2[j,o] = sum_i feat[j,i]*b2[i*16+o]
// out[l,o] = sum_j ( FB2[j,o] + sum_h relu(dt*w1_h+b1_h) * FW2[j,h,o] )
//
// R15: base = R8 (best measured: 128 blocks x 1024 thr, TILE_L=8) + hoisted
// activation table S[ll][jb][h] = relu(dt*w1+b1), built fused into phase 1
// (2 items/thread, id==address). Phase-2 FULL path reads S via broadcast
// LDS.128 instead of recomputing relu per o-thread (16x duplication removed).

namespace cc {
constexpr int LEN     = 512;
constexpr int BSZ     = 2;
constexpr int IN_CH   = 16;
constexpr int OUT_CH  = 16;
constexpr int HID     = 8;
constexpr int BAND    = 30;                 // j in [l-29, l]
constexpr int TILE_L  = 8;
constexpr int NJMAX   = BAND - 1 + TILE_L;  // 37
constexpr int OSTR    = 12;                 // 8 FW2 + FB2 + pad (16B aligned)
constexpr int JSTR    = OUT_CH * OSTR;      // 192 floats per jr row
constexpr int W2STR   = 272;                // padded w2 row (16h offset -> bank-split)
constexpr int NTHR    = 1024;
constexpr int NGRP    = 8;
}

__global__ __launch_bounds__(1024, 1)
void cc1d_fused_kernel(const float* __restrict__ times,
                       const float* __restrict__ features,
                       const int* __restrict__ lengths_i32,   // int32 or int64 layout
                       const void* __restrict__ true_ids_raw, // u8 or int32 layout
                       const float* __restrict__ w1,
                       const float* __restrict__ b1,
                       const float* __restrict__ w2,
                       const float* __restrict__ b2,
                       float* __restrict__ out)
{
    using namespace cc;
    __shared__ __align__(16) float feats[NJMAX * IN_CH];
    __shared__ __align__(16) float fw2s[NJMAX * JSTR];
    __shared__ __align__(16) float w2s[HID * W2STR];
    __shared__ __align__(16) float b2s[IN_CH * OUT_CH];      // [i*16+o]
    __shared__ __align__(16) float ss[TILE_L * 256];         // S[ll<<8 | jb<<3 | h]
    __shared__ float ts[NJMAX];
    __shared__ float w1s[HID], b1s[HID];
    __shared__ float partial[(NGRP - 1) * 128];

    const int b       = blockIdx.y;
    const int l_start = blockIdx.x * TILE_L;
    const bool FULL   = (blockIdx.x >= 4);    // band never clips: j0=l_start-29, nj=37
    const int t       = threadIdx.x;
    const int g       = t >> 7;         // work-split group 0..7 (warp-uniform)
    const int m       = t & 127;
    const int h       = m >> 4;         // hidden unit (phase1) / l_local (phase2)
    const int o       = m & 15;
    const int lane    = t & 31;

    const int j0 = FULL ? (l_start - (BAND - 1)) : 0;
    const int nj = FULL ? NJMAX : (l_start + TILE_L);

    // ---- (1) barrier-critical loads FIRST: feats float4 (<=148 threads, 1 iter) ----
    float4 fv = make_float4(0.f, 0.f, 0.f, 0.f);
    const int jr_f = t >> 2;
    const int j_f  = j0 + jr_f;
    const bool do_feat = (t < nj * 4);
    if (do_feat)
        fv = ((const float4*)features)[(b * LEN + j_f) * 4 + (t & 3)];

    // ---- (2) layout detection: 1 LDG/thread over first 128B (L1/L2-shared).
    // int32-bool values are 0/1 => any nonzero byte above byte-0 => byte layout.
    const unsigned int v0 = ((const unsigned int*)true_ids_raw)[lane];

    // ---- (3) other cooperative loads (contiguous, few wavefronts) ----
    if (t < 512) {   // w2: 2048 floats as float4 into padded-stride shared
        const float4 wv = ((const float4*)w2)[t];
        const int hh = t >> 6, c4 = t & 63;
        *(float4*)&w2s[hh * W2STR + c4 * 4] = wv;
    }
    else if (t < 512 + 64) {  // b2: 256 floats as float4
        ((float4*)b2s)[t - 512] = ((const float4*)b2)[t - 512];
    }
    else if (t < 576 + HID) { w1s[t - 576] = w1[t - 576]; b1s[t - 576] = b1[t - 576]; }
    else if (t >= 640 && t - 640 < nj) ts[t - 640] = times[b * LEN + j0 + (t - 640)];

    int len_pref = 0;   // only g==0 stores output; avoid 2048 junk LDGs
    if (t < 128) {
        const int hw = __ldg(&lengths_i32[1]);   // hi word 0 <=> int64 (lengths >= 1)
        len_pref = (hw == 0) ? __ldg(&lengths_i32[2 * b]) : __ldg(&lengths_i32[b]);
    }

    // ---- resolve detection, fetch mask byte, select, store feats ----
    const bool byte_layout =
        __ballot_sync(0xFFFFFFFFu, (v0 & 0xFFFFFF00u) != 0u) != 0u;
    if (do_feat) {
        // LSB byte of an int32 bool equals its value (little-endian)
        const int bidx = (b * LEN + j_f) << (byte_layout ? 0 : 2);
        if (((const unsigned char*)true_ids_raw)[bidx] == 0)
            fv = make_float4(0.f, 0.f, 0.f, 0.f);
        ((float4*)feats)[t] = fv;
    }
    __syncthreads();   // feats, ts, w1s, b2s, w2s visible

    // per-thread w2 column from shared (conflict-free: 16h offset splits halves)
    float w2col[IN_CH];
    #pragma unroll
    for (int i = 0; i < IN_CH; i++)
        w2col[i] = w2s[h * W2STR + i * 16 + o];

    // ---- phase 1a: FW2/FB2 transposed store; 5 predicated rows per group ----
    {
        const int jr_base = g * 5;
        #pragma unroll
        for (int u = 0; u < 5; u++) {
            const int jr = jr_base + u;
            if (jr < nj) {
                const float4* fj4 = (const float4*)&feats[jr * IN_CH];
                float4 fa = fj4[0], fb = fj4[1], fc = fj4[2], fd = fj4[3];
                float aA = 0.0f, aB = 0.0f;
                aA = fmaf(fa.x, w2col[0], aA); aB = fmaf(fb.x, w2col[4], aB);
                aA = fmaf(fa.y, w2col[1], aA); aB = fmaf(fb.y, w2col[5], aB);
                aA = fmaf(fa.z, w2col[2], aA); aB = fmaf(fb.z, w2col[6], aB);
                aA = fmaf(fa.w, w2col[3], aA); aB = fmaf(fb.w, w2col[7], aB);
                aA = fmaf(fc.x, w2col[8],  aA); aB = fmaf(fd.x, w2col[12], aB);
                aA = fmaf(fc.y, w2col[9],  aA); aB = fmaf(fd.y, w2col[13], aB);
                aA = fmaf(fc.z, w2col[10], aA); aB = fmaf(fd.z, w2col[14], aB);
                aA = fmaf(fc.w, w2col[11], aA); aB = fmaf(fd.w, w2col[15], aB);
                fw2s[jr * JSTR + o * OSTR + h] = aA + aB;
                if (h == (jr & 7)) {       // one o-row of threads per jr does FB2
                    float bA = 0.0f, bB = 0.0f;
                    bA = fmaf(fa.x, b2s[0 * 16 + o],  bA); bB = fmaf(fb.x, b2s[4 * 16 + o],  bB);
                    bA = fmaf(fa.y, b2s[1 * 16 + o],  bA); bB = fmaf(fb.y, b2s[5 * 16 + o],  bB);
                    bA = fmaf(fa.z, b2s[2 * 16 + o],  bA); bB = fmaf(fb.z, b2s[6 * 16 + o],  bB);
                    bA = fmaf(fa.w, b2s[3 * 16 + o],  bA); bB = fmaf(fb.w, b2s[7 * 16 + o],  bB);
                    bA = fmaf(fc.x, b2s[8 * 16 + o],  bA); bB = fmaf(fd.x, b2s[12 * 16 + o], bB);
                    bA = fmaf(fc.y, b2s[9 * 16 + o],  bA); bB = fmaf(fd.y, b2s[13 * 16 + o], bB);
                    bA = fmaf(fc.z, b2s[10 * 16 + o], bA); bB = fmaf(fd.z, b2s[14 * 16 + o], bB);
                    bA = fmaf(fc.w, b2s[11 * 16 + o], bA); bB = fmaf(fd.w, b2s[15 * 16 + o], bB);
                    fw2s[jr * JSTR + o * OSTR + 8] = bA + bB;
                }
            }
        }
    }

    // ---- phase 1b (FULL only): activation table S[ll][jb][h], 2 items/thread ----
    // id bits: h = id&7, jb = (id>>3)&31, ll = id>>8; S address == id. jr = ll + jb.
    if (FULL) {
        #pragma unroll
        for (int r = 0; r < 2; r++) {
            const int id = t + r * NTHR;
            const int hh = id & 7;
            const int jb = (id >> 3) & 31;
            const int ll = id >> 8;
            if (jb < BAND) {
                const float dt = ts[ll + (BAND - 1)] - ts[ll + jb];
                float hv = fmaf(dt, w1s[hh], b1s[hh]);
                ss[id] = hv > 0.f ? hv : 0.f;
            }
        }
    }
    __syncthreads();

    // ---- phase 2: band reduction per (l, o) ----
    float acc0 = 0.0f, acc1 = 0.0f;

    if (FULL) {
        // band for l_local=h is jr in [h, h+29]; chunk g covers jb = 4g..4g+3
        const int ll = h;
        #pragma unroll
        for (int u = 0; u < 4; u++) {
            const int jb = g * 4 + u;
            if (jb < BAND) {      // only g==7, u>=2 fail; compile-time per u at g known? runtime g -> cheap
                const float* frp = &fw2s[(ll + jb) * JSTR + o * OSTR];
                const float4 fA = *(const float4*)frp;        // FW2 h=0..3
                const float4 fB = *(const float4*)(frp + 4);  // FW2 h=4..7
                const float* sp = &ss[(ll << 8) + (jb << 3)]; // broadcast across o
                const float4 sA = *(const float4*)sp;
                const float4 sB = *(const float4*)(sp + 4);
                float a0 = frp[8];                            // FB2 term
                float a1 = 0.0f;
                a0 = fmaf(sA.x, fA.x, a0); a1 = fmaf(sA.y, fA.y, a1);
                a0 = fmaf(sA.z, fA.z, a0); a1 = fmaf(sA.w, fA.w, a1);
                a0 = fmaf(sB.x, fB.x, a0); a1 = fmaf(sB.y, fB.y, a1);
                a0 = fmaf(sB.z, fB.z, a0); a1 = fmaf(sB.w, fB.w, a1);
                acc0 += a0; acc1 += a1;
            }
        }
    } else {
        // generic edge path (blockIdx.x < 4): j0 == 0
        float w1r[HID], b1r[HID];
        #pragma unroll
        for (int k = 0; k < HID; k++) { w1r[k] = w1s[k]; b1r[k] = b1s[k]; }
        const int lr = l_start + h;
        const float tl = ts[lr];
        int jr_lo = lr - (BAND - 1); if (jr_lo < 0) jr_lo = 0;
        const int js = jr_lo + g * 4;
        #pragma unroll
        for (int u = 0; u < 4; u++) {
            const int jr = js + u;
            if (jr <= lr) {
                const float dt = tl - ts[jr];
                const float* frp = &fw2s[jr * JSTR + o * OSTR];
                const float4 fA = *(const float4*)frp;
                const float4 fB = *(const float4*)(frp + 4);
                float a0 = frp[8];
                float a1 = 0.0f;
                float hv;
                hv = fmaf(dt, w1r[0], b1r[0]); hv = hv > 0.f ? hv : 0.f; a0 = fmaf(hv, fA.x, a0);
                hv = fmaf(dt, w1r[1], b1r[1]); hv = hv > 0.f ? hv : 0.f; a1 = fmaf(hv, fA.y, a1);
                hv = fmaf(dt, w1r[2], b1r[2]); hv = hv > 0.f ? hv : 0.f; a0 = fmaf(hv, fA.z, a0);
                hv = fmaf(dt, w1r[3], b1r[3]); hv = hv > 0.f ? hv : 0.f; a1 = fmaf(hv, fA.w, a1);
                hv = fmaf(dt, w1r[4], b1r[4]); hv = hv > 0.f ? hv : 0.f; a0 = fmaf(hv, fB.x, a0);
                hv = fmaf(dt, w1r[5], b1r[5]); hv = hv > 0.f ? hv : 0.f; a1 = fmaf(hv, fB.y, a1);
                hv = fmaf(dt, w1r[6], b1r[6]); hv = hv > 0.f ? hv : 0.f; a0 = fmaf(hv, fB.z, a0);
                hv = fmaf(dt, w1r[7], b1r[7]); hv = hv > 0.f ? hv : 0.f; a1 = fmaf(hv, fB.w, a1);
                acc0 += a0; acc1 += a1;
            }
        }
    }
    float acc = acc0 + acc1;

    if (g > 0) partial[(g - 1) * 128 + m] = acc;
    __syncthreads();

    if (g == 0) {
        float p0 = partial[m]           + partial[128 + m];
        float p1 = partial[2 * 128 + m] + partial[3 * 128 + m];
        float p2 = partial[4 * 128 + m] + partial[5 * 128 + m];
        acc += (p0 + p1) + (p2 + partial[6 * 128 + m]);
        const int l = l_start + h;
        const bool valid = l <= 6 * (len_pref - 1);
        out[(b * LEN + l) * OUT_CH + o] = valid ? acc : 0.0f;
    }
}

extern "C" void kernel_launch(void* const* d_in, const int* in_sizes, int n_in,
                              void* d_out, int out_size) {
    using namespace cc;
    // dict order: times, features, lengths, true_ids, [sim_size], w1, b1, w2, b2
    const float* times    = (const float*)d_in[0];
    const float* features = (const float*)d_in[1];
    const int*   lengths  = (const int*)d_in[2];
    const void*  tids     = d_in[3];

    int base = 4;
    if (n_in >= 9 && in_sizes[4] == 1) base = 5;  // sim_size scalar occupies slot 4

    const float* w1 = (const float*)d_in[base + 0];
    const float* b1 = (const float*)d_in[base + 1];
    const float* w2 = (const float*)d_in[base + 2];
    const float* b2 = (const float*)d_in[base + 3];
    float*       out = (float*)d_out;

    dim3 grid(LEN / TILE_L, BSZ);   // 64 x 2 = 128 blocks, 1 per SM
    cc1d_fused_kernel<<<grid, NTHR>>>(times, features, lengths, tids,
                                      w1, b1, w2, b2, out);
}